// round 17
// baseline (speedup 1.0000x reference)
#include <cuda_runtime.h>
#include <cuda_fp16.h>
#include <cstdint>

// ---------------- problem constants ----------------
#define IN_C   64
#define IMG_H  256
#define IMG_W  256
#define OUT_C  128
#define OUT_H  254
#define OUT_W  254
#define NPOS   (IMG_H * IMG_W)          // 65536
#define NTAPS  9
#define OUT_HW (OUT_H * OUT_W)

// CTA tile: M=128 (all oc), N=128 (positions), K=64 per tap (R6 config)
#define N_TILE 128

// smem layout
#define SM_A         0                  // 2 stages x 16KB (w tap tile, 128x64 fp16, SW128)
#define A_STAGE      16384
#define SM_B         32768              // 3 strips (kh) x 136 rows x 128B (NHWC, SW128)
#define STRIP_STRIDE 17408              // 136*128
#define SM_SCR       84992              // fp32 staging: 32 ic-rows x 544B (136 floats)
#define SCR_ROW_F    136                // floats per scratch row
#define SMEM_TOTAL   102400             // 84992 + 17408

// ---------------- device scratch (no allocs allowed) ----------------
__device__ __align__(1024) __half g_w[NTAPS * OUT_C * IN_C]; // [tap][oc][ic] fp16

// ---------------- helpers ----------------
__device__ __forceinline__ uint32_t smem_u32(const void* p) {
    uint32_t a;
    asm("{ .reg .u64 t; cvta.to.shared.u64 t, %1; cvt.u32.u64 %0, t; }" : "=r"(a) : "l"(p));
    return a;
}
__device__ __forceinline__ uint32_t sw128(uint32_t o) { return o ^ ((o >> 3) & 0x70); }
__device__ __forceinline__ void cp_async16(uint32_t dst, const void* src) {
    asm volatile("cp.async.cg.shared.global [%0], [%1], 16;" :: "r"(dst), "l"(src) : "memory");
}
__device__ __forceinline__ void cp_commit() {
    asm volatile("cp.async.commit_group;" ::: "memory");
}
template <int N>
__device__ __forceinline__ void cp_wait() {
    asm volatile("cp.async.wait_group %0;" :: "n"(N) : "memory");
}
__device__ __forceinline__ void ldsm4(uint32_t* r, uint32_t addr) {
    asm volatile("ldmatrix.sync.aligned.m8n8.x4.shared.b16 {%0,%1,%2,%3}, [%4];"
                 : "=r"(r[0]), "=r"(r[1]), "=r"(r[2]), "=r"(r[3]) : "r"(addr));
}
__device__ __forceinline__ void mma16816(float* d, const uint32_t* a, uint32_t b0, uint32_t b1) {
    asm volatile("mma.sync.aligned.m16n8k16.row.col.f32.f16.f16.f32 "
                 "{%0,%1,%2,%3}, {%4,%5,%6,%7}, {%8,%9}, {%0,%1,%2,%3};"
                 : "+f"(d[0]), "+f"(d[1]), "+f"(d[2]), "+f"(d[3])
                 : "r"(a[0]), "r"(a[1]), "r"(a[2]), "r"(a[3]), "r"(b0), "r"(b1));
}

// ---------------- prep kernel: weight repack only ----------------
// w[oc][ic][3][3] fp32 -> g_w[tap][oc][ic] fp16.  grid 288 x 256.
__global__ __launch_bounds__(256) void prep_w(const float* __restrict__ w) {
    const int idx = blockIdx.x * 256 + threadIdx.x;     // < 73728
    const int tap = idx >> 13;
    const int oc  = (idx >> 6) & 127;
    const int ic  = idx & 63;
    g_w[idx] = __float2half(w[((size_t)oc * IN_C + ic) * NTAPS + tap]);
}

// ---------------- main HMMA conv kernel (R6 mainloop + in-CTA transpose) --------
// grid (2, 254): blockIdx.x = col tile (128 wide), blockIdx.y = output row
__global__ __launch_bounds__(256, 2)
void conv_hmma(const float* __restrict__ x,
               const float* __restrict__ bias, float* __restrict__ out)
{
    extern __shared__ char smem[];
    const uint32_t sbase = smem_u32(smem);
    float* scr = reinterpret_cast<float*>(smem + SM_SCR);
    const int tid  = threadIdx.x;
    const int lane = tid & 31;
    const int wid  = tid >> 5;
    const int wm   = wid & 1;            // oc 0-63 / 64-127
    const int wn   = wid >> 1;           // 0..3, 32 positions each
    const int oh   = blockIdx.y;
    const int ow0  = blockIdx.x * N_TILE;

    // ldmatrix per-lane address components (validated mapping)
    const int rowA = ((lane >> 3) & 1) * 8 + (lane & 7);
    const int kbA  = (lane >> 4) * 16;
    const int rowB = ((lane >> 4) & 1) * 8 + (lane & 7);
    const int kbB  = ((lane >> 3) & 1) * 16;

    float acc[4][4][4];
#pragma unroll
    for (int a = 0; a < 4; a++)
#pragma unroll
        for (int b = 0; b < 4; b++)
#pragma unroll
            for (int c = 0; c < 4; c++) acc[a][b][c] = 0.0f;

    // ---- load one weight tap tile into stage s ----
    auto issue_A = [&](int tap, int s) {
        const __half* src = g_w + (size_t)tap * OUT_C * IN_C;
        const uint32_t sb = sbase + SM_A + s * A_STAGE;
#pragma unroll
        for (int i = 0; i < 4; i++) {
            const uint32_t chunk = tid + i * 256;          // 0..1023
            cp_async16(sb + sw128(chunk * 16), src + chunk * 8);
        }
    };

    issue_A(0, 0);
    cp_commit();            // g0: A0
    issue_A(1, 1);
    cp_commit();            // g1: A1

    // ---- build the 3 B strips in-CTA: CHW fp32 -> NHWC fp16 (SW128) ----
    // Processed as 6 passes (3 strips x 2 ic-halves) through the fp32 scratch.
#pragma unroll 1
    for (int sh = 0; sh < 6; sh++) {
        const int s   = sh >> 1;         // strip (kh)
        const int icb = (sh & 1) * 32;   // ic half base
        const int y0s = (oh + s) * IMG_W + ow0;

        // stage: 32 rows x 33 float4 (132 floats covering 130 needed)
        for (int j = tid; j < 32 * 33; j += 256) {
            const int row = j / 33;
            const int c4  = j - row * 33;
            size_t idx = (size_t)(icb + row) * NPOS + (size_t)y0s + (size_t)c4 * 4;
            if (idx + 3 >= (size_t)IN_C * NPOS) idx = (size_t)IN_C * NPOS - 4;  // tail clamp
            float4 f = *reinterpret_cast<const float4*>(x + idx);
            *reinterpret_cast<float4*>(scr + row * SCR_ROW_F + c4 * 4) = f;
        }
        __syncthreads();

        // convert: 130 pos x 4 chunks of 8 ic -> fp16 NHWC SW128
        for (int q = tid; q < 520; q += 256) {
            const int ic4 = q / 130;     // 0..3
            const int pos = q - ic4 * 130;
            uint32_t pk[4];
#pragma unroll
            for (int jj = 0; jj < 4; jj++) {
                float f0 = scr[(ic4 * 8 + 2 * jj)     * SCR_ROW_F + pos];
                float f1 = scr[(ic4 * 8 + 2 * jj + 1) * SCR_ROW_F + pos];
                __half2 hh = __floats2half2_rn(f0, f1);
                pk[jj] = *reinterpret_cast<uint32_t*>(&hh);
            }
            const uint32_t off = (uint32_t)pos * 128 + (uint32_t)(icb + ic4 * 8) * 2;
            *reinterpret_cast<uint4*>(smem + SM_B + s * STRIP_STRIDE + sw128(off)) =
                make_uint4(pk[0], pk[1], pk[2], pk[3]);
        }
        __syncthreads();
    }

    // ---- mainloop (R6 verbatim) ----
#pragma unroll 1
    for (int t = 0; t < NTAPS; t++) {
        if (t < NTAPS - 1) cp_wait<1>(); else cp_wait<0>();
        __syncthreads();

        const int kh = t / 3;
        const int kw = t - kh * 3;
        const uint32_t aBase = sbase + SM_A + (t & 1) * A_STAGE;
        const uint32_t bBase = sbase + SM_B + kh * STRIP_STRIDE;

#pragma unroll
        for (int kc = 0; kc < 4; kc++) {
            uint32_t a[4][4];
#pragma unroll
            for (int mi = 0; mi < 4; mi++) {
                const uint32_t o = (uint32_t)(wm * 64 + mi * 16 + rowA) * 128 + kc * 32 + kbA;
                ldsm4(a[mi], aBase + sw128(o));
            }
#pragma unroll
            for (int nj = 0; nj < 2; nj++) {
                uint32_t b[4];
                const uint32_t brow = (uint32_t)(kw + wn * 32 + nj * 16 + rowB);
                const uint32_t o = brow * 128 + kc * 32 + kbB;
                ldsm4(b, bBase + sw128(o));
#pragma unroll
                for (int mi = 0; mi < 4; mi++) {
                    mma16816(acc[mi][nj * 2],     a[mi], b[0], b[1]);
                    mma16816(acc[mi][nj * 2 + 1], a[mi], b[2], b[3]);
                }
            }
        }
        __syncthreads();
        if (t + 2 < NTAPS) { issue_A(t + 2, t & 1); cp_commit(); }
    }

    // ---- epilogue: direct gmem stores ----
#pragma unroll
    for (int mi = 0; mi < 4; mi++) {
        const int oc0 = wm * 64 + mi * 16 + (lane >> 2);
        const float b0 = bias[oc0];
        const float b1 = bias[oc0 + 8];
#pragma unroll
        for (int ni = 0; ni < 4; ni++) {
            const int owp = ow0 + wn * 32 + ni * 8 + (lane & 3) * 2;
            if (owp < OUT_W) {
                float2 v0 = make_float2(acc[mi][ni][0] + b0, acc[mi][ni][1] + b0);
                float2 v1 = make_float2(acc[mi][ni][2] + b1, acc[mi][ni][3] + b1);
                *reinterpret_cast<float2*>(out + (size_t)oc0 * OUT_HW + oh * OUT_W + owp) = v0;
                *reinterpret_cast<float2*>(out + (size_t)(oc0 + 8) * OUT_HW + oh * OUT_W + owp) = v1;
            }
        }
    }
}

// ---------------- launch ----------------
extern "C" void kernel_launch(void* const* d_in, const int* in_sizes, int n_in,
                              void* d_out, int out_size)
{
    const float* x    = (const float*)d_in[0];
    const float* w    = (const float*)d_in[1];
    const float* bias = (const float*)d_in[2];
    float* out        = (float*)d_out;

    cudaFuncSetAttribute(conv_hmma, cudaFuncAttributeMaxDynamicSharedMemorySize, SMEM_TOTAL);

    prep_w<<<(NTAPS * OUT_C * IN_C) / 256, 256>>>(w);
    conv_hmma<<<dim3(2, OUT_H), 256, SMEM_TOTAL>>>(x, bias, out);
}